// round 1
// baseline (speedup 1.0000x reference)
#include <cuda_runtime.h>
#include <cuda_bf16.h>
#include <math.h>

typedef unsigned long long u64;

#define N_OSC 50
#define N_PER 40
#define STEPS 100
#define BATCH 8192
#define NPAIR 25              // oscillator pairs
#define NUNITS (256 * NPAIR)  // 256 batch-groups of 32 x 25 osc-pairs = 6400

// ---------------- packed f32x2 helpers ----------------
#define FMA2(d, a, b, c) \
    asm("fma.rn.f32x2 %0, %1, %2, %3;" : "=l"(d) : "l"(a), "l"(b), "l"(c))
#define PACK2(v, lo, hi) \
    asm("mov.b64 %0, {%1, %2};" : "=l"(v) : "f"(lo), "f"(hi))
#define UNPACK2(lo, hi, v) \
    asm("mov.b64 {%0, %1}, %2;" : "=f"(lo), "=f"(hi) : "l"(v))

// ---------------- device scratch (no allocs allowed) ----------------
__device__ float g_x3[BATCH * 100];            // o0 initial states, [b][100]
__device__ float g_direct[BATCH];              // direct torque term per batch
__device__ float g_cpack[NPAIR * N_PER * 12];  // packed per-(osc-pair, n) constants
__device__ float g_tqp[NPAIR * STEPS * BATCH]; // per-osc-pair torque partials
__device__ float g_tq[STEPS * BATCH];          // reduced torque (pre direct)
__device__ unsigned int g_ticket;

// ============================================================
// K0: pack constants + reset ticket
// layout per (op, n): {e0A,e0B,e1A,e1B, obA,obB,d0A,d0B, d1A,d1B,wA,wB}
// ============================================================
__global__ void prep_kernel(const float* __restrict__ enc,
                            const float* __restrict__ obias,
                            const float* __restrict__ dec,
                            const float* __restrict__ fc4_w) {
    int i = blockIdx.x * blockDim.x + threadIdx.x;
    if (i == 0) g_ticket = 0u;
    if (i < NPAIR * N_PER) {
        int op = i / N_PER, n = i % N_PER;
        int oA = 2 * op, oB = 2 * op + 1;
        float* dst = g_cpack + (size_t)i * 12;
        dst[0]  = enc[oA * 80 + n * 2 + 0];
        dst[1]  = enc[oB * 80 + n * 2 + 0];
        dst[2]  = enc[oA * 80 + n * 2 + 1];
        dst[3]  = enc[oB * 80 + n * 2 + 1];
        dst[4]  = obias[oA * 40 + n];
        dst[5]  = obias[oB * 40 + n];
        dst[6]  = dec[oA * 80 + n];        // dec[oA][0][n]
        dst[7]  = dec[oB * 80 + n];
        dst[8]  = dec[oA * 80 + 40 + n];   // dec[oA][1][n]
        dst[9]  = dec[oB * 80 + 40 + n];
        dst[10] = fc4_w[oA * 40 + n];
        dst[11] = fc4_w[oB * 40 + n];
    }
}

// ============================================================
// K1: fused MLP per batch row: h -> (direct, h2 -> x3)
// block = 128 threads = one batch row
// ============================================================
__global__ __launch_bounds__(128) void mlp_kernel(
    const float* __restrict__ x,
    const float* __restrict__ fc1_w, const float* __restrict__ fc1_b,
    const float* __restrict__ fc2_w, const float* __restrict__ fc2_b,
    const float* __restrict__ fc3_w, const float* __restrict__ fc3_b,
    const float* __restrict__ fcd_w, const float* __restrict__ fcd_b) {
    __shared__ float4 s_h4[32];
    __shared__ float4 s_h24[32];
    const float* s_h  = (const float*)s_h4;
    const float* s_h2 = (const float*)s_h24;

    int b = blockIdx.x;
    int j = threadIdx.x;
    float x0 = x[b * 2 + 0], x1 = x[b * 2 + 1];

    // h = relu(x @ fc1_w.T + fc1_b)
    float h = fmaxf(fmaf(x0, fc1_w[j * 2 + 0], fmaf(x1, fc1_w[j * 2 + 1], fc1_b[j])), 0.f);
    ((float*)s_h4)[j] = h;
    __syncthreads();

    // h2 = relu(h @ fc2_w.T + fc2_b)
    float acc = fc2_b[j];
    const float4* w4 = (const float4*)(fc2_w + (size_t)j * 128);
#pragma unroll
    for (int k = 0; k < 32; ++k) {
        float4 w = __ldg(w4 + k);
        float4 hh = s_h4[k];
        acc = fmaf(w.x, hh.x, acc);
        acc = fmaf(w.y, hh.y, acc);
        acc = fmaf(w.z, hh.z, acc);
        acc = fmaf(w.w, hh.w, acc);
    }
    ((float*)s_h24)[j] = fmaxf(acc, 0.f);

    // direct = h @ fcd_w.T + fcd_b  (warp 0; s_h is final)
    if (j < 32) {
        float p = s_h[j] * fcd_w[j] + s_h[j + 32] * fcd_w[j + 32] +
                  s_h[j + 64] * fcd_w[j + 64] + s_h[j + 96] * fcd_w[j + 96];
#pragma unroll
        for (int o = 16; o > 0; o >>= 1) p += __shfl_down_sync(0xffffffffu, p, o);
        if (j == 0) g_direct[b] = p + fcd_b[0];
    }
    __syncthreads();

    // x3 = h2 @ fc3_w.T + fc3_b   (100 outputs)
    if (j < 100) {
        float a2 = fc3_b[j];
        const float4* w34 = (const float4*)(fc3_w + (size_t)j * 128);
#pragma unroll
        for (int k = 0; k < 32; ++k) {
            float4 w = __ldg(w34 + k);
            float4 hh = s_h24[k];
            a2 = fmaf(w.x, hh.x, a2);
            a2 = fmaf(w.y, hh.y, a2);
            a2 = fmaf(w.z, hh.z, a2);
            a2 = fmaf(w.w, hh.w, a2);
        }
        g_x3[(size_t)b * 100 + j] = a2;
    }
}

// ============================================================
// K2: oscillator scan. Unit = (batch-group of 32, osc-pair).
// lane = batch element; f32x2 packs the 2 oscillators of the pair.
// Ticket-based stealing balances across 148 SMs.
// ============================================================
__global__ __launch_bounds__(256, 4) void osc_kernel() {
    __shared__ float s_c[NPAIR * N_PER * 12];  // 48000 B
    for (int i = threadIdx.x; i < NPAIR * N_PER * 3; i += 256)
        ((float4*)s_c)[i] = ((const float4*)g_cpack)[i];
    __syncthreads();

    const int lane = threadIdx.x & 31;
    u64 dt2;
    PACK2(dt2, 0.01f, 0.01f);

    for (;;) {
        unsigned u = 0;
        if (lane == 0) u = atomicAdd(&g_ticket, 1u);
        u = __shfl_sync(0xffffffffu, u, 0);
        if (u >= NUNITS) break;

        const unsigned op = u % NPAIR;
        const unsigned bg = u / NPAIR;
        const int b = bg * 32 + lane;

        // initial o state: x3[b][4op .. 4op+3] = {oxA, oyA, oxB, oyB}
        float4 o0 = __ldg((const float4*)(g_x3 + (size_t)b * 100 + op * 4));
        u64 ox2, oy2;
        PACK2(ox2, o0.x, o0.z);
        PACK2(oy2, o0.y, o0.w);

        const ulonglong2* cp = ((const ulonglong2*)s_c) + (size_t)op * (N_PER * 3ull / 2 * 2); // op*120
        float* tq_out = g_tqp + (size_t)op * (STEPS * BATCH) + b;

        for (int t = 0; t < STEPS; ++t) {
            u64 dx = 0ull, dy = 0ull, tq = 0ull;
#pragma unroll
            for (int n = 0; n < N_PER; ++n) {
                ulonglong2 c0 = cp[n * 3 + 0];  // {e0A,e0B | e1A,e1B}
                ulonglong2 c1 = cp[n * 3 + 1];  // {obA,obB | d0A,d0B}
                ulonglong2 c2 = cp[n * 3 + 2];  // {d1A,d1B | wA,wB}
                u64 t2;
                FMA2(t2, ox2, c0.x, c1.x);
                FMA2(t2, oy2, c0.y, t2);
                float aL, aH;
                UNPACK2(aL, aH, t2);
                aL = fmaxf(aL, 0.f);
                aH = fmaxf(aH, 0.f);
                u64 a2;
                PACK2(a2, aL, aH);
                FMA2(dx, c1.y, a2, dx);
                FMA2(dy, c2.x, a2, dy);
                FMA2(tq, c2.y, a2, tq);
            }
            FMA2(ox2, dt2, dx, ox2);
            FMA2(oy2, dt2, dy, oy2);
            float tl, th;
            UNPACK2(tl, th, tq);
            tq_out[t * BATCH] = tl + th;   // deterministic per-unit slot
        }
    }
}

// ============================================================
// K3: reduce 25 osc-pair partials -> g_tq  (coalesced, BW-bound)
// ============================================================
__global__ void reduce_kernel() {
    int i = blockIdx.x * blockDim.x + threadIdx.x;  // < STEPS*BATCH
    float s = 0.f;
#pragma unroll
    for (int p = 0; p < NPAIR; ++p) s += g_tqp[(size_t)p * (STEPS * BATCH) + i];
    g_tq[i] = s;
}

// ============================================================
// K4: pendulum scan + output writes
// out layout: l_states [100][8192][2] then torques [100][8192]
// ============================================================
__global__ void scan_kernel(const float* __restrict__ x,
                            const float* __restrict__ fc4_b,
                            float* __restrict__ out) {
    int b = blockIdx.x * blockDim.x + threadIdx.x;  // < BATCH
    float theta = x[b * 2 + 0];
    float omega = 0.f;
    const float dir = g_direct[b] + fc4_b[0];
    float2* outL = (float2*)out;                    // (t*BATCH+b) float2 each
    float* outT = out + STEPS * BATCH * 2;
    for (int t = 0; t < STEPS; ++t) {
        float tau = g_tq[t * BATCH + b] + dir;
        float alpha = tau - sinf(theta) - 0.1f * omega;  // M_G_LC=1, I=1
        float th2 = theta + 0.01f * omega;
        float om2 = omega + 0.01f * alpha;
        outL[t * BATCH + b] = make_float2(th2, om2);
        outT[t * BATCH + b] = tau;
        theta = th2;
        omega = om2;
    }
}

// ============================================================
extern "C" void kernel_launch(void* const* d_in, const int* in_sizes, int n_in,
                              void* d_out, int out_size) {
    const float* x     = (const float*)d_in[0];
    const float* fc1_w = (const float*)d_in[1];
    const float* fc1_b = (const float*)d_in[2];
    const float* fc2_w = (const float*)d_in[3];
    const float* fc2_b = (const float*)d_in[4];
    const float* fc3_w = (const float*)d_in[5];
    const float* fc3_b = (const float*)d_in[6];
    const float* fcd_w = (const float*)d_in[7];
    const float* fcd_b = (const float*)d_in[8];
    const float* enc   = (const float*)d_in[9];
    const float* obias = (const float*)d_in[10];
    const float* dec   = (const float*)d_in[11];
    const float* fc4_w = (const float*)d_in[12];
    const float* fc4_b = (const float*)d_in[13];
    float* out = (float*)d_out;

    prep_kernel<<<8, 128>>>(enc, obias, dec, fc4_w);
    mlp_kernel<<<BATCH, 128>>>(x, fc1_w, fc1_b, fc2_w, fc2_b, fc3_w, fc3_b, fcd_w, fcd_b);
    osc_kernel<<<148 * 4, 256>>>();
    reduce_kernel<<<(STEPS * BATCH) / 256, 256>>>();
    scan_kernel<<<BATCH / 256, 256>>>(x, fc4_b, out);
}

// round 2
// speedup vs baseline: 7.6030x; 7.6030x over previous
#include <cuda_runtime.h>
#include <cuda_bf16.h>
#include <math.h>

typedef unsigned long long u64;

#define N_OSC 50
#define N_PER 40
#define STEPS 100
#define BATCH 8192
#define NPAIR 25              // oscillator pairs
#define NUNITS (256 * NPAIR)  // 256 batch-groups of 32 x 25 osc-pairs = 6400

// ---------------- packed f32x2 helpers ----------------
#define FMA2(d, a, b, c) \
    asm("fma.rn.f32x2 %0, %1, %2, %3;" : "=l"(d) : "l"(a), "l"(b), "l"(c))
#define PACK2(v, lo, hi) \
    asm("mov.b64 %0, {%1, %2};" : "=l"(v) : "f"(lo), "f"(hi))
#define UNPACK2(lo, hi, v) \
    asm("mov.b64 {%0, %1}, %2;" : "=f"(lo), "=f"(hi) : "l"(v))

// ---------------- device scratch (no allocs allowed) ----------------
__device__ float g_x3[BATCH * 100];            // o0 initial states, [b][100]
__device__ float g_direct[BATCH];              // direct torque term per batch
__device__ float g_cpack[NPAIR * N_PER * 12];  // packed per-(osc-pair, n) constants
__device__ float g_tqp[NPAIR * STEPS * BATCH]; // per-osc-pair torque partials
__device__ float g_tq[STEPS * BATCH];          // reduced torque (pre direct)
__device__ unsigned int g_ticket;

// ============================================================
// K0: pack constants + reset ticket
// layout per (op, n): {e0A,e0B,e1A,e1B, obA,obB,d0A,d0B, d1A,d1B,wA,wB}
// ============================================================
__global__ void prep_kernel(const float* __restrict__ enc,
                            const float* __restrict__ obias,
                            const float* __restrict__ dec,
                            const float* __restrict__ fc4_w) {
    int i = blockIdx.x * blockDim.x + threadIdx.x;
    if (i == 0) g_ticket = 0u;
    if (i < NPAIR * N_PER) {
        int op = i / N_PER, n = i % N_PER;
        int oA = 2 * op, oB = 2 * op + 1;
        float* dst = g_cpack + (size_t)i * 12;
        dst[0]  = enc[oA * 80 + n * 2 + 0];
        dst[1]  = enc[oB * 80 + n * 2 + 0];
        dst[2]  = enc[oA * 80 + n * 2 + 1];
        dst[3]  = enc[oB * 80 + n * 2 + 1];
        dst[4]  = obias[oA * 40 + n];
        dst[5]  = obias[oB * 40 + n];
        dst[6]  = dec[oA * 80 + n];        // dec[oA][0][n]
        dst[7]  = dec[oB * 80 + n];
        dst[8]  = dec[oA * 80 + 40 + n];   // dec[oA][1][n]
        dst[9]  = dec[oB * 80 + 40 + n];
        dst[10] = fc4_w[oA * 40 + n];
        dst[11] = fc4_w[oB * 40 + n];
    }
}

// ============================================================
// K1: fused MLP per batch row: h -> (direct, h2 -> x3)
// block = 128 threads = one batch row
// ============================================================
__global__ __launch_bounds__(128) void mlp_kernel(
    const float* __restrict__ x,
    const float* __restrict__ fc1_w, const float* __restrict__ fc1_b,
    const float* __restrict__ fc2_w, const float* __restrict__ fc2_b,
    const float* __restrict__ fc3_w, const float* __restrict__ fc3_b,
    const float* __restrict__ fcd_w, const float* __restrict__ fcd_b) {
    __shared__ float4 s_h4[32];
    __shared__ float4 s_h24[32];
    const float* s_h  = (const float*)s_h4;

    int b = blockIdx.x;
    int j = threadIdx.x;
    float x0 = x[b * 2 + 0], x1 = x[b * 2 + 1];

    // h = relu(x @ fc1_w.T + fc1_b)
    float h = fmaxf(fmaf(x0, fc1_w[j * 2 + 0], fmaf(x1, fc1_w[j * 2 + 1], fc1_b[j])), 0.f);
    ((float*)s_h4)[j] = h;
    __syncthreads();

    // h2 = relu(h @ fc2_w.T + fc2_b)
    float acc = fc2_b[j];
    const float4* w4 = (const float4*)(fc2_w + (size_t)j * 128);
#pragma unroll
    for (int k = 0; k < 32; ++k) {
        float4 w = __ldg(w4 + k);
        float4 hh = s_h4[k];
        acc = fmaf(w.x, hh.x, acc);
        acc = fmaf(w.y, hh.y, acc);
        acc = fmaf(w.z, hh.z, acc);
        acc = fmaf(w.w, hh.w, acc);
    }
    ((float*)s_h24)[j] = fmaxf(acc, 0.f);

    // direct = h @ fcd_w.T + fcd_b  (warp 0; s_h is final)
    if (j < 32) {
        float p = s_h[j] * fcd_w[j] + s_h[j + 32] * fcd_w[j + 32] +
                  s_h[j + 64] * fcd_w[j + 64] + s_h[j + 96] * fcd_w[j + 96];
#pragma unroll
        for (int o = 16; o > 0; o >>= 1) p += __shfl_down_sync(0xffffffffu, p, o);
        if (j == 0) g_direct[b] = p + fcd_b[0];
    }
    __syncthreads();

    // x3 = h2 @ fc3_w.T + fc3_b   (100 outputs)
    if (j < 100) {
        float a2 = fc3_b[j];
        const float4* w34 = (const float4*)(fc3_w + (size_t)j * 128);
#pragma unroll
        for (int k = 0; k < 32; ++k) {
            float4 w = __ldg(w34 + k);
            float4 hh = s_h24[k];
            a2 = fmaf(w.x, hh.x, a2);
            a2 = fmaf(w.y, hh.y, a2);
            a2 = fmaf(w.z, hh.z, a2);
            a2 = fmaf(w.w, hh.w, a2);
        }
        g_x3[(size_t)b * 100 + j] = a2;
    }
}

// ============================================================
// K2: oscillator scan. Unit = (batch-group of 32, osc-pair).
// lane = batch element; f32x2 packs the 2 oscillators of the pair.
// Ticket-based stealing balances across 148 SMs.
// NOTE: launch_bounds(256,2) -> 128 regs/thread. The previous
// (256,4) capped regs at 64 and spilled the unrolled loop to
// local memory (the 20x slowdown). Unroll is also bounded to 8.
// ============================================================
__global__ __launch_bounds__(256, 2) void osc_kernel() {
    __shared__ float s_c[NPAIR * N_PER * 12];  // 48000 B
    for (int i = threadIdx.x; i < NPAIR * N_PER * 3; i += 256)
        ((float4*)s_c)[i] = ((const float4*)g_cpack)[i];
    __syncthreads();

    const int lane = threadIdx.x & 31;
    u64 dt2;
    PACK2(dt2, 0.01f, 0.01f);

    for (;;) {
        unsigned u = 0;
        if (lane == 0) u = atomicAdd(&g_ticket, 1u);
        u = __shfl_sync(0xffffffffu, u, 0);
        if (u >= NUNITS) break;

        const unsigned op = u % NPAIR;
        const unsigned bg = u / NPAIR;
        const int b = bg * 32 + lane;

        // initial o state: x3[b][4op .. 4op+3] = {oxA, oyA, oxB, oyB}
        float4 o0 = __ldg((const float4*)(g_x3 + (size_t)b * 100 + op * 4));
        u64 ox2, oy2;
        PACK2(ox2, o0.x, o0.z);
        PACK2(oy2, o0.y, o0.w);

        const ulonglong2* cp = ((const ulonglong2*)s_c) + (size_t)op * 120;
        float* tq_out = g_tqp + (size_t)op * (STEPS * BATCH) + b;

        for (int t = 0; t < STEPS; ++t) {
            u64 dx = 0ull, dy = 0ull, tq = 0ull;
#pragma unroll 8
            for (int n = 0; n < N_PER; ++n) {
                ulonglong2 c0 = cp[n * 3 + 0];  // {e0A,e0B | e1A,e1B}
                ulonglong2 c1 = cp[n * 3 + 1];  // {obA,obB | d0A,d0B}
                ulonglong2 c2 = cp[n * 3 + 2];  // {d1A,d1B | wA,wB}
                u64 t2;
                FMA2(t2, ox2, c0.x, c1.x);
                FMA2(t2, oy2, c0.y, t2);
                float aL, aH;
                UNPACK2(aL, aH, t2);
                aL = fmaxf(aL, 0.f);
                aH = fmaxf(aH, 0.f);
                u64 a2;
                PACK2(a2, aL, aH);
                FMA2(dx, c1.y, a2, dx);
                FMA2(dy, c2.x, a2, dy);
                FMA2(tq, c2.y, a2, tq);
            }
            FMA2(ox2, dt2, dx, ox2);
            FMA2(oy2, dt2, dy, oy2);
            float tl, th;
            UNPACK2(tl, th, tq);
            tq_out[t * BATCH] = tl + th;   // deterministic per-unit slot
        }
    }
}

// ============================================================
// K3: reduce 25 osc-pair partials -> g_tq  (coalesced, BW-bound)
// ============================================================
__global__ void reduce_kernel() {
    int i = blockIdx.x * blockDim.x + threadIdx.x;  // < STEPS*BATCH
    float s = 0.f;
#pragma unroll
    for (int p = 0; p < NPAIR; ++p) s += g_tqp[(size_t)p * (STEPS * BATCH) + i];
    g_tq[i] = s;
}

// ============================================================
// K4: pendulum scan + output writes
// out layout: l_states [100][8192][2] then torques [100][8192]
// ============================================================
__global__ void scan_kernel(const float* __restrict__ x,
                            const float* __restrict__ fc4_b,
                            float* __restrict__ out) {
    int b = blockIdx.x * blockDim.x + threadIdx.x;  // < BATCH
    float theta = x[b * 2 + 0];
    float omega = 0.f;
    const float dir = g_direct[b] + fc4_b[0];
    float2* outL = (float2*)out;                    // (t*BATCH+b) float2 each
    float* outT = out + STEPS * BATCH * 2;
    for (int t = 0; t < STEPS; ++t) {
        float tau = g_tq[t * BATCH + b] + dir;
        float alpha = tau - sinf(theta) - 0.1f * omega;  // M_G_LC=1, I=1
        float th2 = theta + 0.01f * omega;
        float om2 = omega + 0.01f * alpha;
        outL[t * BATCH + b] = make_float2(th2, om2);
        outT[t * BATCH + b] = tau;
        theta = th2;
        omega = om2;
    }
}

// ============================================================
extern "C" void kernel_launch(void* const* d_in, const int* in_sizes, int n_in,
                              void* d_out, int out_size) {
    const float* x     = (const float*)d_in[0];
    const float* fc1_w = (const float*)d_in[1];
    const float* fc1_b = (const float*)d_in[2];
    const float* fc2_w = (const float*)d_in[3];
    const float* fc2_b = (const float*)d_in[4];
    const float* fc3_w = (const float*)d_in[5];
    const float* fc3_b = (const float*)d_in[6];
    const float* fcd_w = (const float*)d_in[7];
    const float* fcd_b = (const float*)d_in[8];
    const float* enc   = (const float*)d_in[9];
    const float* obias = (const float*)d_in[10];
    const float* dec   = (const float*)d_in[11];
    const float* fc4_w = (const float*)d_in[12];
    const float* fc4_b = (const float*)d_in[13];
    float* out = (float*)d_out;

    prep_kernel<<<8, 128>>>(enc, obias, dec, fc4_w);
    mlp_kernel<<<BATCH, 128>>>(x, fc1_w, fc1_b, fc2_w, fc2_b, fc3_w, fc3_b, fcd_w, fcd_b);
    osc_kernel<<<148 * 4, 256>>>();
    reduce_kernel<<<(STEPS * BATCH) / 256, 256>>>();
    scan_kernel<<<BATCH / 256, 256>>>(x, fc4_b, out);
}